// round 4
// baseline (speedup 1.0000x reference)
#include <cuda_runtime.h>
#include <cuda_fp16.h>
#include <stdint.h>
#include <math.h>

// ---------------- problem constants ----------------
#define MDIM 16384      // B*S
#define NDIM 2048       // F
#define KDIM 2048       // D
#define TM   128        // CTA tile M
#define TN   256        // CTA tile N
#define TKC  64         // K per pipeline stage
#define KITERS (KDIM/TKC)   // 32
#define EPSV 1e-6f

// SMEM layout (per stage): Ah | Al | Bh | Bl, rows padded to 72 halves = 144B
#define ROWB   144                    // bytes per padded row (16B aligned, conflict-free)
#define AH_OFF 0
#define AL_OFF (TM*ROWB)              // 18432
#define BH_OFF (2*TM*ROWB)            // 36864
#define BL_OFF (2*TM*ROWB + TN*ROWB)  // 73728
#define STAGE_BYTES (2*TM*ROWB + 2*TN*ROWB)   // 110592
#define SMEM_BYTES  (2*STAGE_BYTES)           // 221184

// ---------------- scratch ----------------
__device__ __half g_x_hi[33554432];
__device__ __half g_x_lo[33554432];
__device__ __half g_w_hi[4194304];
__device__ __half g_w_lo[4194304];
__device__ float  g_x_sq[MDIM];
__device__ float  g_w_sq[NDIM];

// ---------------- PTX helpers ----------------
__device__ __forceinline__ uint32_t smem_u32(const void* p) {
    uint32_t r;
    asm("{ .reg .u64 t; cvta.to.shared.u64 t, %1; cvt.u32.u64 %0, t; }" : "=r"(r) : "l"(p));
    return r;
}

__device__ __forceinline__ void cp16(uint32_t dst, const void* src) {
    asm volatile("cp.async.cg.shared.global [%0], [%1], 16;" :: "r"(dst), "l"(src) : "memory");
}
__device__ __forceinline__ void cp_commit() {
    asm volatile("cp.async.commit_group;" ::: "memory");
}
template <int N>
__device__ __forceinline__ void cp_wait() {
    asm volatile("cp.async.wait_group %0;" :: "n"(N) : "memory");
}

// m16n8k16 row.col f16 -> f32
__device__ __forceinline__ void mma16816(float* c, const uint32_t* a, uint32_t b0, uint32_t b1) {
    asm volatile(
        "mma.sync.aligned.m16n8k16.row.col.f32.f16.f16.f32 "
        "{%0,%1,%2,%3}, {%4,%5,%6,%7}, {%8,%9}, {%0,%1,%2,%3};"
        : "+f"(c[0]), "+f"(c[1]), "+f"(c[2]), "+f"(c[3])
        : "r"(a[0]), "r"(a[1]), "r"(a[2]), "r"(a[3]), "r"(b0), "r"(b1));
}

// ---------------- pre-pass: fp32 -> (hi,lo) fp16 split + row sum-of-squares ----
__global__ __launch_bounds__(256) void split_kernel(const float* __restrict__ x,
                                                    const float* __restrict__ w) {
    int row = blockIdx.x;
    const float* src;
    __half *hi, *lo;
    float* sq;
    if (row < MDIM) {
        src = x + (size_t)row * KDIM;
        hi = g_x_hi + (size_t)row * KDIM;
        lo = g_x_lo + (size_t)row * KDIM;
        sq = g_x_sq + row;
    } else {
        int r = row - MDIM;
        src = w + (size_t)r * KDIM;
        hi = g_w_hi + (size_t)r * KDIM;
        lo = g_w_lo + (size_t)r * KDIM;
        sq = g_w_sq + r;
    }
    float acc = 0.f;
    for (int j = threadIdx.x * 4; j < KDIM; j += 256 * 4) {
        float4 v = *reinterpret_cast<const float4*>(src + j);
        __half h0 = __float2half_rn(v.x), h1 = __float2half_rn(v.y);
        __half h2 = __float2half_rn(v.z), h3 = __float2half_rn(v.w);
        __half l0 = __float2half_rn(v.x - __half2float(h0));
        __half l1 = __float2half_rn(v.y - __half2float(h1));
        __half l2 = __float2half_rn(v.z - __half2float(h2));
        __half l3 = __float2half_rn(v.w - __half2float(h3));
        *reinterpret_cast<__half2*>(hi + j)     = __halves2half2(h0, h1);
        *reinterpret_cast<__half2*>(hi + j + 2) = __halves2half2(h2, h3);
        *reinterpret_cast<__half2*>(lo + j)     = __halves2half2(l0, l1);
        *reinterpret_cast<__half2*>(lo + j + 2) = __halves2half2(l2, l3);
        acc += v.x * v.x + v.y * v.y + v.z * v.z + v.w * v.w;
    }
    __shared__ float red[8];
    #pragma unroll
    for (int o = 16; o > 0; o >>= 1) acc += __shfl_xor_sync(0xffffffffu, acc, o);
    if ((threadIdx.x & 31) == 0) red[threadIdx.x >> 5] = acc;
    __syncthreads();
    if (threadIdx.x < 8) {
        float v = red[threadIdx.x];
        #pragma unroll
        for (int o = 4; o > 0; o >>= 1) v += __shfl_xor_sync(0xffu, v, o);
        if (threadIdx.x == 0) *sq = v;
    }
}

// ---------------- main GEMM + Yat epilogue ----------------
// grid = (MDIM/TM) * (NDIM/TN) = 128*8 = 1024, block = 256 (8 warps of 64x64)
__global__ __launch_bounds__(256, 1) void yat_gemm(float* __restrict__ out,
                                                   const float* __restrict__ alpha,
                                                   const float* __restrict__ bias) {
    extern __shared__ char smem[];
    const uint32_t smem_base = smem_u32(smem);

    const int tid = threadIdx.x;
    const int mtile = blockIdx.x >> 3;
    const int ntile = blockIdx.x & 7;
    const int m0 = mtile * TM;
    const int n0 = ntile * TN;

    const __half* xh = g_x_hi + (size_t)m0 * KDIM;
    const __half* xl = g_x_lo + (size_t)m0 * KDIM;
    const __half* wh = g_w_hi + (size_t)n0 * KDIM;
    const __half* wl = g_w_lo + (size_t)n0 * KDIM;

    // ---- per-thread cp.async chunk coordinates (16B chunks, 8 per 128B row) ----
    // A matrices: 128 rows * 8 chunks = 1024 chunks -> 4 iters of 256 threads
    // B matrices: 256 rows * 8 chunks = 2048 chunks -> 8 iters
    auto load_stage = [&](int chunk) {
        const uint32_t sb = smem_base + (uint32_t)(chunk & 1) * STAGE_BYTES;
        const int kk = chunk * TKC;
        #pragma unroll
        for (int it = 0; it < 4; it++) {
            int q = tid + 256 * it;
            int r = q >> 3, c = q & 7;
            uint32_t so = (uint32_t)r * ROWB + (uint32_t)c * 16;
            size_t go = (size_t)r * KDIM + kk + c * 8;
            cp16(sb + AH_OFF + so, xh + go);
            cp16(sb + AL_OFF + so, xl + go);
        }
        #pragma unroll
        for (int it = 0; it < 8; it++) {
            int q = tid + 256 * it;
            int r = q >> 3, c = q & 7;
            uint32_t so = (uint32_t)r * ROWB + (uint32_t)c * 16;
            size_t go = (size_t)r * KDIM + kk + c * 8;
            cp16(sb + BH_OFF + so, wh + go);
            cp16(sb + BL_OFF + so, wl + go);
        }
    };

    // ---- warp/lane geometry ----
    const int warp = tid >> 5;
    const int lane = tid & 31;
    const int wm = warp & 1;        // 2 warps along M (64 each)
    const int wn = warp >> 1;       // 4 warps along N (64 each)
    const int g  = lane >> 2;       // group id 0..7
    const int tg = lane & 3;        // thread-in-group 0..3

    const uint32_t a_base = (uint32_t)(wm * 64 + g) * ROWB + (uint32_t)tg * 4;
    const uint32_t b_base = (uint32_t)(wn * 64 + g) * ROWB + (uint32_t)tg * 4;

    float acc[4][8][4];
    #pragma unroll
    for (int mi = 0; mi < 4; mi++)
        #pragma unroll
        for (int ni = 0; ni < 8; ni++)
            #pragma unroll
            for (int e = 0; e < 4; e++) acc[mi][ni][e] = 0.f;

    // ---- pipeline ----
    load_stage(0);
    cp_commit();

    for (int i = 0; i < KITERS; i++) {
        if (i + 1 < KITERS) {
            load_stage(i + 1);
            cp_commit();
            cp_wait<1>();
        } else {
            cp_wait<0>();
        }
        __syncthreads();

        const char* sb = smem + (size_t)(i & 1) * STAGE_BYTES;
        const char* Ah = sb + AH_OFF + a_base;
        const char* Al = sb + AL_OFF + a_base;
        const char* Bh = sb + BH_OFF + b_base;
        const char* Bl = sb + BL_OFF + b_base;

        #pragma unroll
        for (int ks = 0; ks < 4; ks++) {
            const int kb = ks * 32;   // 16 halves = 32 bytes per k-step
            uint32_t ah[4][4], al[4][4];
            #pragma unroll
            for (int mi = 0; mi < 4; mi++) {
                const char* pa = Ah + mi * (16 * ROWB) + kb;
                ah[mi][0] = *(const uint32_t*)(pa);
                ah[mi][1] = *(const uint32_t*)(pa + 8 * ROWB);
                ah[mi][2] = *(const uint32_t*)(pa + 16);
                ah[mi][3] = *(const uint32_t*)(pa + 8 * ROWB + 16);
                const char* pl = Al + mi * (16 * ROWB) + kb;
                al[mi][0] = *(const uint32_t*)(pl);
                al[mi][1] = *(const uint32_t*)(pl + 8 * ROWB);
                al[mi][2] = *(const uint32_t*)(pl + 16);
                al[mi][3] = *(const uint32_t*)(pl + 8 * ROWB + 16);
            }
            #pragma unroll
            for (int ni = 0; ni < 8; ni++) {
                const char* pb = Bh + ni * (8 * ROWB) + kb;
                uint32_t bh0 = *(const uint32_t*)(pb);
                uint32_t bh1 = *(const uint32_t*)(pb + 16);
                const char* pc = Bl + ni * (8 * ROWB) + kb;
                uint32_t bl0 = *(const uint32_t*)(pc);
                uint32_t bl1 = *(const uint32_t*)(pc + 16);
                #pragma unroll
                for (int mi = 0; mi < 4; mi++)
                    mma16816(acc[mi][ni], ah[mi], bh0, bh1);   // x_hi * w_hi
                #pragma unroll
                for (int mi = 0; mi < 4; mi++)
                    mma16816(acc[mi][ni], ah[mi], bl0, bl1);   // x_hi * w_lo
                #pragma unroll
                for (int mi = 0; mi < 4; mi++)
                    mma16816(acc[mi][ni], al[mi], bh0, bh1);   // x_lo * w_hi
            }
        }
        __syncthreads();
    }

    // ---- epilogue: Yat transform from register accumulators ----
    const float a = *alpha;
    const float base = sqrtf((float)NDIM) / logf(1.0f + (float)NDIM);
    const float scale = powf(base, a);

    #pragma unroll
    for (int mi = 0; mi < 4; mi++) {
        const int r0 = m0 + wm * 64 + mi * 16 + g;
        const float xs0 = g_x_sq[r0];
        const float xs1 = g_x_sq[r0 + 8];
        #pragma unroll
        for (int ni = 0; ni < 8; ni++) {
            const int col = n0 + wn * 64 + ni * 8 + tg * 2;
            const float ws0 = __ldg(&g_w_sq[col]);
            const float ws1 = __ldg(&g_w_sq[col + 1]);
            const float bi0 = __ldg(&bias[col]);
            const float bi1 = __ldg(&bias[col + 1]);
            float y;
            float2 o;
            // row r0
            y = acc[mi][ni][0];
            o.x = scale * y * y / (xs0 + ws0 - 2.0f * y + EPSV) + bi0;
            y = acc[mi][ni][1];
            o.y = scale * y * y / (xs0 + ws1 - 2.0f * y + EPSV) + bi1;
            *reinterpret_cast<float2*>(out + (size_t)r0 * NDIM + col) = o;
            // row r0+8
            y = acc[mi][ni][2];
            o.x = scale * y * y / (xs1 + ws0 - 2.0f * y + EPSV) + bi0;
            y = acc[mi][ni][3];
            o.y = scale * y * y / (xs1 + ws1 - 2.0f * y + EPSV) + bi1;
            *reinterpret_cast<float2*>(out + (size_t)(r0 + 8) * NDIM + col) = o;
        }
    }
}

// ---------------- launch ----------------
extern "C" void kernel_launch(void* const* d_in, const int* in_sizes, int n_in,
                              void* d_out, int out_size) {
    (void)in_sizes; (void)n_in; (void)out_size;
    const float* x     = (const float*)d_in[0];
    const float* w     = (const float*)d_in[1];
    const float* alpha = (const float*)d_in[2];
    const float* bias  = (const float*)d_in[3];
    float* out = (float*)d_out;

    static int smem_set = 0;
    if (!smem_set) {
        cudaFuncSetAttribute(yat_gemm, cudaFuncAttributeMaxDynamicSharedMemorySize, SMEM_BYTES);
        smem_set = 1;
    }

    split_kernel<<<MDIM + NDIM, 256>>>(x, w);
    yat_gemm<<<(MDIM / TM) * (NDIM / TN), 256, SMEM_BYTES>>>(out, alpha, bias);
}